// round 11
// baseline (speedup 1.0000x reference)
#include <cuda_runtime.h>

// ---------------------------------------------------------------------------
// STGCN fused kernel for GB300 (sm_103a)  — R9/R10: l1tex reduction
// x: [64, 512, 2, 21, 2]  ->  out: [64, 512, 2, 64]  (fp32)
// CTA = (b, hand, T-tile of 32); 672 threads = (v, c); BN folded by prep.
// Changes vs measured R8 baseline (occ 32.4% capped, L1=61.9% binding):
//  - conv phases B/D: weights hoisted to registers, 2 passes of 4 i4-groups
//    with thread-private fp32 partials (weight LDS -83%, kills 4-wf bursts)
//  - C2: all 8 weight vectors hoisted (-83% weight LDS)
//  - FC: 256 threads x (1 o x 8 t)  (wavefronts/output 2.0 -> 1.5)
// ---------------------------------------------------------------------------

#define NPARAMS 7904

#define OFF_A    0      // 441  : normalized adjacency [v][u]
#define OFF_W0T  448    // 64   : gcn0 weights [ci][c]
#define OFF_GB0  512    // 32   : gcn0 bias
#define OFF_WT0  544    // 3072 : tcn0 folded, [k][i4][c][4]
#define OFF_B0   3616   // 32
#define OFF_RW   3648   // 64   : residual conv folded [ci][c]
#define OFF_RB   3712   // 32
#define OFF_W1T  3744   // 1024 : gcn1 weights [i4][c][4]
#define OFF_GB1  4768   // 32
#define OFF_WT1  4800   // 3072 : tcn1 folded, [k][i4][c][4]
#define OFF_B1   7872   // 32

#define SM_XS    7904          // 36*42  = 1512
#define SM_BUF2  9416          // 34*672 = 22848  (y1 scratch / h1 / h2)
#define SM_BUF1  32264         // 36*672 = 24192  (y2 / z1 / z2 / fc stage)
#define SM_TOTALF 56456        // 225824 bytes

__device__ float d_params[NPARAMS];
__device__ float d_fcwT[64 * 672];   // fc weights: [o][p], p = v*32+c

typedef unsigned long long u64;

static __device__ __forceinline__ float4 ld4(const float* p) {
    return *reinterpret_cast<const float4*>(p);
}
static __device__ __forceinline__ void st4(float* p, float4 v) {
    *reinterpret_cast<float4*>(p) = v;
}
static __device__ __forceinline__ ulonglong2 ld2x2(const float* p) {
    return *reinterpret_cast<const ulonglong2*>(p);
}
static __device__ __forceinline__ u64 ffma2(u64 a, u64 b, u64 c) {
    u64 d;
    asm("fma.rn.f32x2 %0, %1, %2, %3;" : "=l"(d) : "l"(a), "l"(b), "l"(c));
    return d;
}
static __device__ __forceinline__ float hsum2(u64 p) {
    float lo, hi;
    asm("mov.b64 {%0, %1}, %2;" : "=f"(lo), "=f"(hi) : "l"(p));
    return lo + hi;
}

// ---------------------------------------------------------------------------
// preload 4 i4-groups x 3 taps of conv weights into regs (12 packed pairs)
// ---------------------------------------------------------------------------
static __device__ __forceinline__ void load_w4(const float* __restrict__ w,
                                               int i40, int c, u64* wlo, u64* whi)
{
#pragma unroll
    for (int j = 0; j < 4; j++)
#pragma unroll
        for (int k = 0; k < 3; k++) {
            ulonglong2 W = ld2x2(w + ((k * 8 + (i40 + j)) * 32 + c) * 4);
            wlo[j * 3 + k] = W.x;
            whi[j * 3 + k] = W.y;
        }
}

// ---------------------------------------------------------------------------
// conv group: U outputs over 4 i4-groups, weights in regs, rolling input window
// bi[slot][v*32+i]; output u sums taps k over in slots s0+u+k, i in [i40*4, i40*4+16)
// ---------------------------------------------------------------------------
template<int U>
__device__ __forceinline__ void conv_group(const float* __restrict__ bi,
                                           int s0, int voff, int i40,
                                           const u64* wlo, const u64* whi,
                                           float* acc)
{
    u64 alo[U], ahi[U];
#pragma unroll
    for (int u = 0; u < U; u++) { alo[u] = 0ull; ahi[u] = 0ull; }
#pragma unroll
    for (int j = 0; j < 4; j++) {
        const float* p = bi + s0 * 672 + voff + (i40 + j) * 4;
        ulonglong2 i0 = ld2x2(p);
        ulonglong2 i1 = ld2x2(p + 672);
#pragma unroll
        for (int u = 0; u < U; u++) {
            ulonglong2 i2 = ld2x2(p + (u + 2) * 672);
            alo[u] = ffma2(wlo[j * 3 + 0], i0.x, alo[u]);
            ahi[u] = ffma2(whi[j * 3 + 0], i0.y, ahi[u]);
            alo[u] = ffma2(wlo[j * 3 + 1], i1.x, alo[u]);
            ahi[u] = ffma2(whi[j * 3 + 1], i1.y, ahi[u]);
            alo[u] = ffma2(wlo[j * 3 + 2], i2.x, alo[u]);
            ahi[u] = ffma2(whi[j * 3 + 2], i2.y, ahi[u]);
            i0 = i1; i1 = i2;
        }
    }
#pragma unroll
    for (int u = 0; u < U; u++) acc[u] = hsum2(alo[u]) + hsum2(ahi[u]);
}

// Phase B pass 0 group: store raw partial (i4 0-3) to buf2
template<int U>
__device__ __forceinline__ void b_pass0(const float* __restrict__ buf1,
                                        float* __restrict__ buf2,
                                        const u64* wlo, const u64* whi,
                                        int s0, int voff, int c)
{
    float acc[U];
    conv_group<U>(buf1, s0, voff, 0, wlo, whi, acc);
#pragma unroll
    for (int u = 0; u < U; u++)
        buf2[(s0 + u) * 672 + voff + c] = acc[u];
}

// Phase B pass 1 group: finalize (i4 4-7) + bias + conv-residual + relu
template<int U>
__device__ __forceinline__ void b_pass1(const float* __restrict__ buf1,
                                        float* __restrict__ buf2,
                                        const float* __restrict__ xs,
                                        const u64* wlo, const u64* whi,
                                        int s0, int voff, int v, int c,
                                        float bias0c, float rw0, float rw1, float rbc)
{
    float acc[U];
    conv_group<U>(buf1, s0, voff, 4, wlo, whi, acc);
#pragma unroll
    for (int u = 0; u < U; u++) {
        int sp = s0 + u;                   // h1 slot, t = t0-1+sp
        float res = fmaf(rw0, xs[(sp + 1) * 42 + v * 2],
                    fmaf(rw1, xs[(sp + 1) * 42 + v * 2 + 1], rbc));
        float part = buf2[sp * 672 + voff + c];   // thread-private partial
        buf2[sp * 672 + voff + c] = fmaxf(part + acc[u] + bias0c + res, 0.0f);
    }
}

// Phase D pass 0 group: partial = h1 + conv(i4 0-3)   (in place in buf2)
template<int U>
__device__ __forceinline__ void d_pass0(const float* __restrict__ buf1,
                                        float* __restrict__ buf2,
                                        const u64* wlo, const u64* whi,
                                        int u0, int voff, int c)
{
    float acc[U];
    conv_group<U>(buf1, u0, voff, 0, wlo, whi, acc);
#pragma unroll
    for (int u = 0; u < U; u++) {
        int slot = u0 + u + 1;             // slot for t = t0+u0+u
        float h1v = buf2[slot * 672 + voff + c];  // thread-private
        buf2[slot * 672 + voff + c] = h1v + acc[u];
    }
}

// Phase D pass 1 group: finalize + bias + relu
template<int U>
__device__ __forceinline__ void d_pass1(const float* __restrict__ buf1,
                                        float* __restrict__ buf2,
                                        const u64* wlo, const u64* whi,
                                        int u0, int voff, int c, float bias1c)
{
    float acc[U];
    conv_group<U>(buf1, u0, voff, 4, wlo, whi, acc);
#pragma unroll
    for (int u = 0; u < U; u++) {
        int slot = u0 + u + 1;
        float part = buf2[slot * 672 + voff + c];
        buf2[slot * 672 + voff + c] = fmaxf(part + acc[u] + bias1c, 0.0f);
    }
}

// Phase C1: graph gather (at its data-movement minimum; quarter-warp phases
// are 128B-contiguous -> conflict-free)
template<int U>
__device__ __forceinline__ void c1_group(const float* __restrict__ h1,
                                         float* __restrict__ z1,
                                         const float* __restrict__ Ah,
                                         int sb, int vv, int ii4)
{
    float4 acc[U];
#pragma unroll
    for (int j = 0; j < U; j++) { acc[j].x = 0.f; acc[j].y = 0.f; acc[j].z = 0.f; acc[j].w = 0.f; }
    for (int u = 0; u < 21; u++) {
        float a = Ah[vv * 21 + u];
#pragma unroll
        for (int j = 0; j < U; j++) {
            float4 in = ld4(h1 + (sb + j) * 672 + u * 32 + ii4 * 4);
            acc[j].x = fmaf(a, in.x, acc[j].x);
            acc[j].y = fmaf(a, in.y, acc[j].y);
            acc[j].z = fmaf(a, in.z, acc[j].z);
            acc[j].w = fmaf(a, in.w, acc[j].w);
        }
    }
#pragma unroll
    for (int j = 0; j < U; j++)
        st4(z1 + (sb + j) * 672 + vv * 32 + ii4 * 4, acc[j]);
}

// Phase C2 group: projection with weights in regs, in-place (warp-private row)
template<int U>
__device__ __forceinline__ void c2_group(float* __restrict__ buf1,
                                         const u64* wlo, const u64* whi,
                                         int sb, int voff, int c, float gb, int tbase)
{
    u64 alo[U], ahi[U];
#pragma unroll
    for (int u = 0; u < U; u++) { alo[u] = 0ull; ahi[u] = 0ull; }
#pragma unroll
    for (int i4 = 0; i4 < 8; i4++) {
#pragma unroll
        for (int u = 0; u < U; u++) {
            ulonglong2 in = ld2x2(buf1 + (sb + u) * 672 + voff + i4 * 4);
            alo[u] = ffma2(wlo[i4], in.x, alo[u]);
            ahi[u] = ffma2(whi[i4], in.y, ahi[u]);
        }
    }
    __syncwarp();   // whole warp (owner of row v) finished reading before overwrite
#pragma unroll
    for (int u = 0; u < U; u++) {
        int t = tbase + u;
        float val = gb + hsum2(alo[u]) + hsum2(ahi[u]);
        buf1[(sb + u) * 672 + voff + c] = ((unsigned)t < 512u) ? val : 0.0f;
    }
}

// ---------------------------------------------------------------------------
// prep kernel
// ---------------------------------------------------------------------------
__global__ void stgcn_prep(const float* __restrict__ gcn_w0, const float* __restrict__ gcn_b0,
                           const float* __restrict__ tcn_w0, const float* __restrict__ tcn_b0,
                           const float* __restrict__ bn_g0, const float* __restrict__ bn_b0,
                           const float* __restrict__ bn_m0, const float* __restrict__ bn_v0,
                           const float* __restrict__ res_w, const float* __restrict__ res_b,
                           const float* __restrict__ res_bn_g, const float* __restrict__ res_bn_b,
                           const float* __restrict__ res_bn_m, const float* __restrict__ res_bn_v,
                           const float* __restrict__ gcn_w1, const float* __restrict__ gcn_b1,
                           const float* __restrict__ tcn_w1, const float* __restrict__ tcn_b1,
                           const float* __restrict__ bn_g1, const float* __restrict__ bn_b1,
                           const float* __restrict__ bn_m1, const float* __restrict__ bn_v1,
                           const float* __restrict__ fc_w)
{
    __shared__ float As[441];
    __shared__ float dg[21];
    int tid = threadIdx.x;
    int gid = blockIdx.x * blockDim.x + tid;
    int gsz = gridDim.x * blockDim.x;

    if (blockIdx.x == 0) {
        for (int i = tid; i < 441; i += blockDim.x) As[i] = 0.0f;
        __syncthreads();
        if (tid == 0) {
            const int ca[20] = {0,1,2,3,0,5,6,7,0,9,10,11,0,13,14,15,0,17,18,19};
            const int cb[20] = {1,2,3,4,5,6,7,8,9,10,11,12,13,14,15,16,17,18,19,20};
            for (int e = 0; e < 20; e++) { As[ca[e]*21+cb[e]] = 1.0f; As[cb[e]*21+ca[e]] = 1.0f; }
            for (int i = 0; i < 21; i++) As[i*21+i] = 1.0f;
        }
        __syncthreads();
        if (tid < 21) {
            float s = 0.0f;
            for (int j = 0; j < 21; j++) s += As[tid*21+j];
            dg[tid] = rsqrtf(s);
        }
        __syncthreads();
        for (int i = tid; i < 441; i += blockDim.x) {
            int r = i / 21, cc = i - r * 21;
            d_params[OFF_A + i] = As[i] * dg[r] * dg[cc];
        }
    }

    for (int i = gid; i < 64; i += gsz) {
        int ci = i >> 5, c = i & 31;
        d_params[OFF_W0T + i] = gcn_w0[c * 2 + ci];
    }
    for (int i = gid; i < 32; i += gsz) d_params[OFF_GB0 + i] = gcn_b0[i];
    for (int i = gid; i < 3072; i += gsz) {
        int cc = i & 3, c = (i >> 2) & 31, i4 = (i >> 7) & 7, k = i >> 10;
        int ii = i4 * 4 + cc;
        float s0 = bn_g0[c] * rsqrtf(bn_v0[c] + 1e-5f);
        d_params[OFF_WT0 + i] = tcn_w0[(c * 32 + ii) * 3 + k] * s0;
    }
    for (int i = gid; i < 32; i += gsz) {
        float s0 = bn_g0[i] * rsqrtf(bn_v0[i] + 1e-5f);
        d_params[OFF_B0 + i] = (tcn_b0[i] - bn_m0[i]) * s0 + bn_b0[i];
    }
    for (int i = gid; i < 64; i += gsz) {
        int ci = i >> 5, c = i & 31;
        float rs = res_bn_g[c] * rsqrtf(res_bn_v[c] + 1e-5f);
        d_params[OFF_RW + i] = res_w[c * 2 + ci] * rs;
    }
    for (int i = gid; i < 32; i += gsz) {
        float rs = res_bn_g[i] * rsqrtf(res_bn_v[i] + 1e-5f);
        d_params[OFF_RB + i] = (res_b[i] - res_bn_m[i]) * rs + res_bn_b[i];
    }
    for (int i = gid; i < 1024; i += gsz) {
        int cc = i & 3, c = (i >> 2) & 31, i4 = i >> 7;
        int ii = i4 * 4 + cc;
        d_params[OFF_W1T + i] = gcn_w1[c * 32 + ii];
    }
    for (int i = gid; i < 32; i += gsz) d_params[OFF_GB1 + i] = gcn_b1[i];
    for (int i = gid; i < 3072; i += gsz) {
        int cc = i & 3, c = (i >> 2) & 31, i4 = (i >> 7) & 7, k = i >> 10;
        int ii = i4 * 4 + cc;
        float s1 = bn_g1[c] * rsqrtf(bn_v1[c] + 1e-5f);
        d_params[OFF_WT1 + i] = tcn_w1[(c * 32 + ii) * 3 + k] * s1;
    }
    for (int i = gid; i < 32; i += gsz) {
        float s1 = bn_g1[i] * rsqrtf(bn_v1[i] + 1e-5f);
        d_params[OFF_B1 + i] = (tcn_b1[i] - bn_m1[i]) * s1 + bn_b1[i];
    }
    for (int i = gid; i < 64 * 672; i += gsz) {
        int o = i / 672, p = i - o * 672;
        int v = p >> 5, c = p & 31;
        d_fcwT[i] = fc_w[o * 672 + c * 21 + v];
    }
}

// ---------------------------------------------------------------------------
// main fused kernel
// ---------------------------------------------------------------------------
__global__ void __launch_bounds__(672, 1)
stgcn_main(const float* __restrict__ x, const float* __restrict__ fcb,
           float* __restrict__ out)
{
    extern __shared__ float sm[];
    const int tid = threadIdx.x;
    const int bx = blockIdx.x;
    const int tile = bx & 15, hand = (bx >> 4) & 1, b = bx >> 5;
    const int t0 = tile * 32;
    const int v = tid >> 5, c = tid & 31, voff = v * 32;

    float* xs   = sm + SM_XS;
    float* buf2 = sm + SM_BUF2;
    float* buf1 = sm + SM_BUF1;
    const float* Ah = sm + OFF_A;

    // ---- load packed params + input tile (halo 2)
    for (int i = tid; i < NPARAMS; i += 672) sm[i] = d_params[i];
    for (int i = tid; i < 36 * 42; i += 672) {
        int s = i / 42, r = i - s * 42;
        int t = t0 - 2 + s;
        float val = 0.0f;
        if ((unsigned)t < 512u)
            val = x[((b * 512 + t) * 2 + hand) * 42 + r];
        xs[i] = val;
    }
    __syncthreads();

    // ---- A1: y1[s][v][ci] = sum_u A[v][u] * x[s][u][ci]   (buf2 scratch)
    for (int i = tid; i < 36 * 42; i += 672) {
        int s = i / 42, r = i - s * 42, vv = r >> 1, ci = r & 1;
        const float* arow = Ah + vv * 21;
        const float* xrow = xs + s * 42 + ci;
        float acc = 0.0f;
#pragma unroll
        for (int u = 0; u < 21; u++) acc = fmaf(arow[u], xrow[u * 2], acc);
        buf2[i] = acc;
    }
    __syncthreads();

    // ---- A2: y2 = gcn0 projection (2 -> 32) into buf1
    {
        float w00 = sm[OFF_W0T + c], w01 = sm[OFF_W0T + 32 + c], g0 = sm[OFF_GB0 + c];
        for (int s = 0; s < 36; s++) {
            int t = t0 - 2 + s;
            float val = 0.0f;
            if ((unsigned)t < 512u)
                val = fmaf(w00, buf2[s * 42 + v * 2], fmaf(w01, buf2[s * 42 + v * 2 + 1], g0));
            buf1[s * 672 + voff + c] = val;
        }
    }
    __syncthreads();

    // ---- B: h1 = relu(tconv0_bn(y2) + res0)  (34 slots into buf2, 2 passes)
    {
        const float* wt0 = sm + OFF_WT0;
        u64 wlo[12], whi[12];
        load_w4(wt0, 0, c, wlo, whi);            // i4 0-3
        b_pass0<6>(buf1, buf2, wlo, whi, 0,  voff, c);
        b_pass0<6>(buf1, buf2, wlo, whi, 6,  voff, c);
        b_pass0<6>(buf1, buf2, wlo, whi, 12, voff, c);
        b_pass0<6>(buf1, buf2, wlo, whi, 18, voff, c);
        b_pass0<6>(buf1, buf2, wlo, whi, 24, voff, c);
        b_pass0<4>(buf1, buf2, wlo, whi, 30, voff, c);

        float bias0c = sm[OFF_B0 + c];
        float rw0 = sm[OFF_RW + c], rw1 = sm[OFF_RW + 32 + c], rbc = sm[OFF_RB + c];
        load_w4(wt0, 4, c, wlo, whi);            // i4 4-7
        b_pass1<6>(buf1, buf2, xs, wlo, whi, 0,  voff, v, c, bias0c, rw0, rw1, rbc);
        b_pass1<6>(buf1, buf2, xs, wlo, whi, 6,  voff, v, c, bias0c, rw0, rw1, rbc);
        b_pass1<6>(buf1, buf2, xs, wlo, whi, 12, voff, v, c, bias0c, rw0, rw1, rbc);
        b_pass1<6>(buf1, buf2, xs, wlo, whi, 18, voff, v, c, bias0c, rw0, rw1, rbc);
        b_pass1<6>(buf1, buf2, xs, wlo, whi, 24, voff, v, c, bias0c, rw0, rw1, rbc);
        b_pass1<4>(buf1, buf2, xs, wlo, whi, 30, voff, v, c, bias0c, rw0, rw1, rbc);
    }
    __syncthreads();

    // ---- C1: z1 = A-gather of h1 (34 slots into buf1)
    {
        int vv  = tid >> 5;
        int ii4 = tid & 7;
        int q   = (tid >> 3) & 3;
        if (q < 3) c1_group<9>(buf2, buf1, Ah, 9 * q, vv, ii4);
        else       c1_group<7>(buf2, buf1, Ah, 27,    vv, ii4);
    }
    __syncthreads();

    // ---- C2: z2 = gcn1 projection, in place in buf1 (weights hoisted)
    {
        const float* w1t = sm + OFF_W1T;
        u64 wlo[8], whi[8];
#pragma unroll
        for (int i4 = 0; i4 < 8; i4++) {
            ulonglong2 W = ld2x2(w1t + (i4 * 32 + c) * 4);
            wlo[i4] = W.x; whi[i4] = W.y;
        }
        float gb1c = sm[OFF_GB1 + c];
        c2_group<6>(buf1, wlo, whi, 0,  voff, c, gb1c, t0 - 1);
        c2_group<6>(buf1, wlo, whi, 6,  voff, c, gb1c, t0 + 5);
        c2_group<6>(buf1, wlo, whi, 12, voff, c, gb1c, t0 + 11);
        c2_group<6>(buf1, wlo, whi, 18, voff, c, gb1c, t0 + 17);
        c2_group<6>(buf1, wlo, whi, 24, voff, c, gb1c, t0 + 23);
        c2_group<4>(buf1, wlo, whi, 30, voff, c, gb1c, t0 + 29);
    }
    __syncthreads();

    // ---- D: h2 = relu(tconv1_bn(z2) + h1)  (buf2 slots 1..32, 2 passes in place)
    {
        const float* wt1 = sm + OFF_WT1;
        u64 wlo[12], whi[12];
        load_w4(wt1, 0, c, wlo, whi);            // i4 0-3: partial = h1 + conv
        d_pass0<6>(buf1, buf2, wlo, whi, 0,  voff, c);
        d_pass0<6>(buf1, buf2, wlo, whi, 6,  voff, c);
        d_pass0<6>(buf1, buf2, wlo, whi, 12, voff, c);
        d_pass0<6>(buf1, buf2, wlo, whi, 18, voff, c);
        d_pass0<6>(buf1, buf2, wlo, whi, 24, voff, c);
        d_pass0<2>(buf1, buf2, wlo, whi, 30, voff, c);

        float bias1c = sm[OFF_B1 + c];
        load_w4(wt1, 4, c, wlo, whi);            // i4 4-7: finalize + relu
        d_pass1<6>(buf1, buf2, wlo, whi, 0,  voff, c, bias1c);
        d_pass1<6>(buf1, buf2, wlo, whi, 6,  voff, c, bias1c);
        d_pass1<6>(buf1, buf2, wlo, whi, 12, voff, c, bias1c);
        d_pass1<6>(buf1, buf2, wlo, whi, 18, voff, c, bias1c);
        d_pass1<6>(buf1, buf2, wlo, whi, 24, voff, c, bias1c);
        d_pass1<2>(buf1, buf2, wlo, whi, 30, voff, c, bias1c);
    }

    // ---- FC: out[t][o] = fc_b[o] + sum_p h2[t][p] * fcwT[o][p]
    // 256 active threads: o = tid&63, tq = tid>>6 (8 t's per thread -> one
    // weight load amortized over 8 broadcast h loads; wf/output 2.0 -> 1.5)
    u64 al[8], ah[8];
#pragma unroll
    for (int tt = 0; tt < 8; tt++) { al[tt] = 0ull; ah[tt] = 0ull; }
    const int o = tid & 63, tq = tid >> 6;
    for (int ch = 0; ch < 2; ch++) {
        const int p0 = ch * 336;
        __syncthreads();   // previous buf1 readers done; buf2 writes visible
        for (int i = tid; i < 64 * 336; i += 672) {
            int oo = i / 336, pi = i - oo * 336;
            buf1[oo * 340 + pi] = d_fcwT[oo * 672 + p0 + pi];
        }
        __syncthreads();
        if (tid < 256) {
            const float* wrow = buf1 + o * 340;
            const float* hb0  = buf2 + (tq * 8 + 1) * 672 + p0;
#pragma unroll 4
            for (int pi4 = 0; pi4 < 84; pi4++) {
                ulonglong2 w = ld2x2(wrow + pi4 * 4);
#pragma unroll
                for (int tt = 0; tt < 8; tt++) {
                    ulonglong2 h = ld2x2(hb0 + tt * 672 + pi4 * 4);
                    al[tt] = ffma2(w.x, h.x, al[tt]);
                    ah[tt] = ffma2(w.y, h.y, ah[tt]);
                }
            }
        }
    }
    if (tid < 256) {
        float bo = fcb[o];
        int tb = t0 + tq * 8;
#pragma unroll
        for (int tt = 0; tt < 8; tt++)
            out[((b * 512 + tb + tt) * 2 + hand) * 64 + o] = hsum2(al[tt]) + hsum2(ah[tt]) + bo;
    }
}

// ---------------------------------------------------------------------------
extern "C" void kernel_launch(void* const* d_in, const int* in_sizes, int n_in,
                              void* d_out, int out_size)
{
    const float* x        = (const float*)d_in[0];
    const float* gcn_w0   = (const float*)d_in[1];
    const float* gcn_b0   = (const float*)d_in[2];
    const float* tcn_w0   = (const float*)d_in[3];
    const float* tcn_b0   = (const float*)d_in[4];
    const float* bn_g0    = (const float*)d_in[5];
    const float* bn_b0    = (const float*)d_in[6];
    const float* bn_m0    = (const float*)d_in[7];
    const float* bn_v0    = (const float*)d_in[8];
    const float* res_w    = (const float*)d_in[9];
    const float* res_b    = (const float*)d_in[10];
    const float* res_bn_g = (const float*)d_in[11];
    const float* res_bn_b = (const float*)d_in[12];
    const float* res_bn_m = (const float*)d_in[13];
    const float* res_bn_v = (const float*)d_in[14];
    const float* gcn_w1   = (const float*)d_in[15];
    const float* gcn_b1   = (const float*)d_in[16];
    const float* tcn_w1   = (const float*)d_in[17];
    const float* tcn_b1   = (const float*)d_in[18];
    const float* bn_g1    = (const float*)d_in[19];
    const float* bn_b1    = (const float*)d_in[20];
    const float* bn_m1    = (const float*)d_in[21];
    const float* bn_v1    = (const float*)d_in[22];
    const float* fc_w     = (const float*)d_in[23];
    const float* fc_b     = (const float*)d_in[24];
    float* out = (float*)d_out;

    const size_t smem_bytes = (size_t)SM_TOTALF * sizeof(float);
    cudaFuncSetAttribute(stgcn_main, cudaFuncAttributeMaxDynamicSharedMemorySize,
                         (int)smem_bytes);

    stgcn_prep<<<96, 256>>>(gcn_w0, gcn_b0, tcn_w0, tcn_b0, bn_g0, bn_b0, bn_m0, bn_v0,
                            res_w, res_b, res_bn_g, res_bn_b, res_bn_m, res_bn_v,
                            gcn_w1, gcn_b1, tcn_w1, tcn_b1, bn_g1, bn_b1, bn_m1, bn_v1,
                            fc_w);
    stgcn_main<<<2048, 672, smem_bytes>>>(x, fc_b, out);
}

// round 12
// speedup vs baseline: 1.0832x; 1.0832x over previous
#include <cuda_runtime.h>

// ---------------------------------------------------------------------------
// STGCN fused kernel for GB300 (sm_103a)  — R11
// x: [64, 512, 2, 21, 2]  ->  out: [64, 512, 2, 64]  (fp32)
// CTA = (b, hand, T-tile of 32); 672 threads = (v, c); BN folded by prep.
// R11 = measured-2702 baseline (batched-load convs, smem weights, 512-thr FC)
//       + C2 weight hoist only (the one R9 change with no added latency).
// ---------------------------------------------------------------------------

#define NPARAMS 7904

#define OFF_A    0      // 441  : normalized adjacency [v][u]
#define OFF_W0T  448    // 64   : gcn0 weights [ci][c]
#define OFF_GB0  512    // 32   : gcn0 bias
#define OFF_WT0  544    // 3072 : tcn0 folded, [k][i4][c][4]
#define OFF_B0   3616   // 32
#define OFF_RW   3648   // 64   : residual conv folded [ci][c]
#define OFF_RB   3712   // 32
#define OFF_W1T  3744   // 1024 : gcn1 weights [i4][c][4]
#define OFF_GB1  4768   // 32
#define OFF_WT1  4800   // 3072 : tcn1 folded, [k][i4][c][4]
#define OFF_B1   7872   // 32

#define SM_XS    7904          // 36*42  = 1512
#define SM_BUF2  9416          // 34*672 = 22848  (y1 scratch / h1 / h2)
#define SM_BUF1  32264         // 36*672 = 24192  (y2 / z1 / z2 / fc stage)
#define SM_TOTALF 56456        // 225824 bytes

__device__ float d_params[NPARAMS];
__device__ float d_fcwT[64 * 672];   // fc weights: [o][p], p = v*32+c

typedef unsigned long long u64;

static __device__ __forceinline__ float4 ld4(const float* p) {
    return *reinterpret_cast<const float4*>(p);
}
static __device__ __forceinline__ void st4(float* p, float4 v) {
    *reinterpret_cast<float4*>(p) = v;
}
static __device__ __forceinline__ ulonglong2 ld2x2(const float* p) {
    return *reinterpret_cast<const ulonglong2*>(p);
}
static __device__ __forceinline__ u64 ffma2(u64 a, u64 b, u64 c) {
    u64 d;
    asm("fma.rn.f32x2 %0, %1, %2, %3;" : "=l"(d) : "l"(a), "l"(b), "l"(c));
    return d;
}
static __device__ __forceinline__ float hsum2(u64 p) {
    float lo, hi;
    asm("mov.b64 {%0, %1}, %2;" : "=f"(lo), "=f"(hi) : "l"(p));
    return lo + hi;
}

// ---------------------------------------------------------------------------
// temporal conv accumulate (R8 style): U outputs, batched input loads (MLP!),
// weights from smem. bi[slot][v*32+i], w [k][i4][c][4]. Inputs warp-broadcast.
// ---------------------------------------------------------------------------
template<int U>
__device__ __forceinline__ void conv_acc2(const float* __restrict__ bi,
                                          const float* __restrict__ w,
                                          int base, int voff, int c,
                                          float* acc)
{
    u64 alo[U], ahi[U];
#pragma unroll
    for (int u = 0; u < U; u++) { alo[u] = 0ull; ahi[u] = 0ull; }
#pragma unroll
    for (int i4 = 0; i4 < 8; i4++) {
        ulonglong2 in[U + 2];
#pragma unroll
        for (int j = 0; j < U + 2; j++)
            in[j] = ld2x2(bi + (base + j) * 672 + voff + i4 * 4);
#pragma unroll
        for (int k = 0; k < 3; k++) {
            ulonglong2 wk = ld2x2(w + ((k * 8 + i4) * 32 + c) * 4);
#pragma unroll
            for (int u = 0; u < U; u++) {
                alo[u] = ffma2(wk.x, in[u + k].x, alo[u]);
                ahi[u] = ffma2(wk.y, in[u + k].y, ahi[u]);
            }
        }
    }
#pragma unroll
    for (int u = 0; u < U; u++) acc[u] = hsum2(alo[u]) + hsum2(ahi[u]);
}

// Phase B: tconv0 + folded bn0 + conv-residual + relu -> h1 (34 slots, buf2)
template<int U>
__device__ __forceinline__ void phaseB(const float* __restrict__ buf1,
                                       float* __restrict__ buf2,
                                       const float* __restrict__ wt0,
                                       const float* __restrict__ xs,
                                       int s0, int voff, int v, int c,
                                       float bias0c, float rw0, float rw1, float rbc)
{
    float acc[U];
    conv_acc2<U>(buf1, wt0, s0, voff, c, acc);
#pragma unroll
    for (int u = 0; u < U; u++) {
        int sp = s0 + u;                   // h1 slot, t = t0-1+sp
        float res = fmaf(rw0, xs[(sp + 1) * 42 + v * 2],
                    fmaf(rw1, xs[(sp + 1) * 42 + v * 2 + 1], rbc));
        buf2[sp * 672 + voff + c] = fmaxf(acc[u] + bias0c + res, 0.0f);
    }
}

// Phase C1: graph gather (data-movement minimum; quarter-warp 128B-contiguous)
template<int U>
__device__ __forceinline__ void c1_group(const float* __restrict__ h1,
                                         float* __restrict__ z1,
                                         const float* __restrict__ Ah,
                                         int sb, int vv, int ii4)
{
    float4 acc[U];
#pragma unroll
    for (int j = 0; j < U; j++) { acc[j].x = 0.f; acc[j].y = 0.f; acc[j].z = 0.f; acc[j].w = 0.f; }
    for (int u = 0; u < 21; u++) {
        float a = Ah[vv * 21 + u];
#pragma unroll
        for (int j = 0; j < U; j++) {
            float4 in = ld4(h1 + (sb + j) * 672 + u * 32 + ii4 * 4);
            acc[j].x = fmaf(a, in.x, acc[j].x);
            acc[j].y = fmaf(a, in.y, acc[j].y);
            acc[j].z = fmaf(a, in.z, acc[j].z);
            acc[j].w = fmaf(a, in.w, acc[j].w);
        }
    }
#pragma unroll
    for (int j = 0; j < U; j++)
        st4(z1 + (sb + j) * 672 + vv * 32 + ii4 * 4, acc[j]);
}

// Phase C2 group: projection with weights HOISTED in regs (R9's proven-cheap
// change: removes 8 x 4-wavefront weight loads per group, adds no traffic),
// in-place (warp-private row v)
template<int U>
__device__ __forceinline__ void c2_group(float* __restrict__ buf1,
                                         const u64* wlo, const u64* whi,
                                         int sb, int voff, int c, float gb, int tbase)
{
    u64 alo[U], ahi[U];
#pragma unroll
    for (int u = 0; u < U; u++) { alo[u] = 0ull; ahi[u] = 0ull; }
#pragma unroll
    for (int i4 = 0; i4 < 8; i4++) {
#pragma unroll
        for (int u = 0; u < U; u++) {
            ulonglong2 in = ld2x2(buf1 + (sb + u) * 672 + voff + i4 * 4);
            alo[u] = ffma2(wlo[i4], in.x, alo[u]);
            ahi[u] = ffma2(whi[i4], in.y, ahi[u]);
        }
    }
    __syncwarp();   // whole warp (owner of row v) finished reading before overwrite
#pragma unroll
    for (int u = 0; u < U; u++) {
        int t = tbase + u;
        float val = gb + hsum2(alo[u]) + hsum2(ahi[u]);
        buf1[(sb + u) * 672 + voff + c] = ((unsigned)t < 512u) ? val : 0.0f;
    }
}

// Phase D: tconv1 + folded bn1 + identity residual + relu (buf2 1..32 in place)
template<int U>
__device__ __forceinline__ void phaseD(const float* __restrict__ buf1,
                                       float* __restrict__ buf2,
                                       const float* __restrict__ wt1,
                                       int u0, int voff, int c, float bias1c)
{
    float acc[U];
    conv_acc2<U>(buf1, wt1, u0, voff, c, acc);
#pragma unroll
    for (int u = 0; u < U; u++) {
        int slot = u0 + u + 1;             // slot for t = t0+u0+u
        float h = acc[u] + bias1c + buf2[slot * 672 + voff + c];   // thread-private
        buf2[slot * 672 + voff + c] = fmaxf(h, 0.0f);
    }
}

// ---------------------------------------------------------------------------
// prep kernel
// ---------------------------------------------------------------------------
__global__ void stgcn_prep(const float* __restrict__ gcn_w0, const float* __restrict__ gcn_b0,
                           const float* __restrict__ tcn_w0, const float* __restrict__ tcn_b0,
                           const float* __restrict__ bn_g0, const float* __restrict__ bn_b0,
                           const float* __restrict__ bn_m0, const float* __restrict__ bn_v0,
                           const float* __restrict__ res_w, const float* __restrict__ res_b,
                           const float* __restrict__ res_bn_g, const float* __restrict__ res_bn_b,
                           const float* __restrict__ res_bn_m, const float* __restrict__ res_bn_v,
                           const float* __restrict__ gcn_w1, const float* __restrict__ gcn_b1,
                           const float* __restrict__ tcn_w1, const float* __restrict__ tcn_b1,
                           const float* __restrict__ bn_g1, const float* __restrict__ bn_b1,
                           const float* __restrict__ bn_m1, const float* __restrict__ bn_v1,
                           const float* __restrict__ fc_w)
{
    __shared__ float As[441];
    __shared__ float dg[21];
    int tid = threadIdx.x;
    int gid = blockIdx.x * blockDim.x + tid;
    int gsz = gridDim.x * blockDim.x;

    if (blockIdx.x == 0) {
        for (int i = tid; i < 441; i += blockDim.x) As[i] = 0.0f;
        __syncthreads();
        if (tid == 0) {
            const int ca[20] = {0,1,2,3,0,5,6,7,0,9,10,11,0,13,14,15,0,17,18,19};
            const int cb[20] = {1,2,3,4,5,6,7,8,9,10,11,12,13,14,15,16,17,18,19,20};
            for (int e = 0; e < 20; e++) { As[ca[e]*21+cb[e]] = 1.0f; As[cb[e]*21+ca[e]] = 1.0f; }
            for (int i = 0; i < 21; i++) As[i*21+i] = 1.0f;
        }
        __syncthreads();
        if (tid < 21) {
            float s = 0.0f;
            for (int j = 0; j < 21; j++) s += As[tid*21+j];
            dg[tid] = rsqrtf(s);
        }
        __syncthreads();
        for (int i = tid; i < 441; i += blockDim.x) {
            int r = i / 21, cc = i - r * 21;
            d_params[OFF_A + i] = As[i] * dg[r] * dg[cc];
        }
    }

    for (int i = gid; i < 64; i += gsz) {
        int ci = i >> 5, c = i & 31;
        d_params[OFF_W0T + i] = gcn_w0[c * 2 + ci];
    }
    for (int i = gid; i < 32; i += gsz) d_params[OFF_GB0 + i] = gcn_b0[i];
    for (int i = gid; i < 3072; i += gsz) {
        int cc = i & 3, c = (i >> 2) & 31, i4 = (i >> 7) & 7, k = i >> 10;
        int ii = i4 * 4 + cc;
        float s0 = bn_g0[c] * rsqrtf(bn_v0[c] + 1e-5f);
        d_params[OFF_WT0 + i] = tcn_w0[(c * 32 + ii) * 3 + k] * s0;
    }
    for (int i = gid; i < 32; i += gsz) {
        float s0 = bn_g0[i] * rsqrtf(bn_v0[i] + 1e-5f);
        d_params[OFF_B0 + i] = (tcn_b0[i] - bn_m0[i]) * s0 + bn_b0[i];
    }
    for (int i = gid; i < 64; i += gsz) {
        int ci = i >> 5, c = i & 31;
        float rs = res_bn_g[c] * rsqrtf(res_bn_v[c] + 1e-5f);
        d_params[OFF_RW + i] = res_w[c * 2 + ci] * rs;
    }
    for (int i = gid; i < 32; i += gsz) {
        float rs = res_bn_g[i] * rsqrtf(res_bn_v[i] + 1e-5f);
        d_params[OFF_RB + i] = (res_b[i] - res_bn_m[i]) * rs + res_bn_b[i];
    }
    for (int i = gid; i < 1024; i += gsz) {
        int cc = i & 3, c = (i >> 2) & 31, i4 = i >> 7;
        int ii = i4 * 4 + cc;
        d_params[OFF_W1T + i] = gcn_w1[c * 32 + ii];
    }
    for (int i = gid; i < 32; i += gsz) d_params[OFF_GB1 + i] = gcn_b1[i];
    for (int i = gid; i < 3072; i += gsz) {
        int cc = i & 3, c = (i >> 2) & 31, i4 = (i >> 7) & 7, k = i >> 10;
        int ii = i4 * 4 + cc;
        float s1 = bn_g1[c] * rsqrtf(bn_v1[c] + 1e-5f);
        d_params[OFF_WT1 + i] = tcn_w1[(c * 32 + ii) * 3 + k] * s1;
    }
    for (int i = gid; i < 32; i += gsz) {
        float s1 = bn_g1[i] * rsqrtf(bn_v1[i] + 1e-5f);
        d_params[OFF_B1 + i] = (tcn_b1[i] - bn_m1[i]) * s1 + bn_b1[i];
    }
    for (int i = gid; i < 64 * 672; i += gsz) {
        int o = i / 672, p = i - o * 672;
        int v = p >> 5, c = p & 31;
        d_fcwT[i] = fc_w[o * 672 + c * 21 + v];
    }
}

// ---------------------------------------------------------------------------
// main fused kernel
// ---------------------------------------------------------------------------
__global__ void __launch_bounds__(672, 1)
stgcn_main(const float* __restrict__ x, const float* __restrict__ fcb,
           float* __restrict__ out)
{
    extern __shared__ float sm[];
    const int tid = threadIdx.x;
    const int bx = blockIdx.x;
    const int tile = bx & 15, hand = (bx >> 4) & 1, b = bx >> 5;
    const int t0 = tile * 32;
    const int v = tid >> 5, c = tid & 31, voff = v * 32;

    float* xs   = sm + SM_XS;
    float* buf2 = sm + SM_BUF2;
    float* buf1 = sm + SM_BUF1;
    const float* Ah = sm + OFF_A;

    // ---- load packed params + input tile (halo 2)
    for (int i = tid; i < NPARAMS; i += 672) sm[i] = d_params[i];
    for (int i = tid; i < 36 * 42; i += 672) {
        int s = i / 42, r = i - s * 42;
        int t = t0 - 2 + s;
        float val = 0.0f;
        if ((unsigned)t < 512u)
            val = x[((b * 512 + t) * 2 + hand) * 42 + r];
        xs[i] = val;
    }
    __syncthreads();

    // ---- A1: y1[s][v][ci] = sum_u A[v][u] * x[s][u][ci]   (buf2 scratch)
    for (int i = tid; i < 36 * 42; i += 672) {
        int s = i / 42, r = i - s * 42, vv = r >> 1, ci = r & 1;
        const float* arow = Ah + vv * 21;
        const float* xrow = xs + s * 42 + ci;
        float acc = 0.0f;
#pragma unroll
        for (int u = 0; u < 21; u++) acc = fmaf(arow[u], xrow[u * 2], acc);
        buf2[i] = acc;
    }
    __syncthreads();

    // ---- A2: y2 = gcn0 projection (2 -> 32) into buf1
    {
        float w00 = sm[OFF_W0T + c], w01 = sm[OFF_W0T + 32 + c], g0 = sm[OFF_GB0 + c];
        for (int s = 0; s < 36; s++) {
            int t = t0 - 2 + s;
            float val = 0.0f;
            if ((unsigned)t < 512u)
                val = fmaf(w00, buf2[s * 42 + v * 2], fmaf(w01, buf2[s * 42 + v * 2 + 1], g0));
            buf1[s * 672 + voff + c] = val;
        }
    }
    __syncthreads();

    // ---- B: h1 = relu(tconv0_bn(y2) + res0)   (34 slots into buf2)
    {
        const float* wt0 = sm + OFF_WT0;
        float bias0c = sm[OFF_B0 + c];
        float rw0 = sm[OFF_RW + c], rw1 = sm[OFF_RW + 32 + c], rbc = sm[OFF_RB + c];
        phaseB<6>(buf1, buf2, wt0, xs, 0,  voff, v, c, bias0c, rw0, rw1, rbc);
        phaseB<6>(buf1, buf2, wt0, xs, 6,  voff, v, c, bias0c, rw0, rw1, rbc);
        phaseB<6>(buf1, buf2, wt0, xs, 12, voff, v, c, bias0c, rw0, rw1, rbc);
        phaseB<6>(buf1, buf2, wt0, xs, 18, voff, v, c, bias0c, rw0, rw1, rbc);
        phaseB<6>(buf1, buf2, wt0, xs, 24, voff, v, c, bias0c, rw0, rw1, rbc);
        phaseB<4>(buf1, buf2, wt0, xs, 30, voff, v, c, bias0c, rw0, rw1, rbc);
    }
    __syncthreads();

    // ---- C1: z1 = A-gather of h1 (34 slots into buf1)
    {
        int vv  = tid >> 5;
        int ii4 = tid & 7;
        int q   = (tid >> 3) & 3;
        if (q < 3) c1_group<9>(buf2, buf1, Ah, 9 * q, vv, ii4);
        else       c1_group<7>(buf2, buf1, Ah, 27,    vv, ii4);
    }
    __syncthreads();

    // ---- C2: z2 = gcn1 projection, in place in buf1 (weights hoisted)
    {
        const float* w1t = sm + OFF_W1T;
        u64 wlo[8], whi[8];
#pragma unroll
        for (int i4 = 0; i4 < 8; i4++) {
            ulonglong2 W = ld2x2(w1t + (i4 * 32 + c) * 4);
            wlo[i4] = W.x; whi[i4] = W.y;
        }
        float gb1c = sm[OFF_GB1 + c];
        c2_group<6>(buf1, wlo, whi, 0,  voff, c, gb1c, t0 - 1);
        c2_group<6>(buf1, wlo, whi, 6,  voff, c, gb1c, t0 + 5);
        c2_group<6>(buf1, wlo, whi, 12, voff, c, gb1c, t0 + 11);
        c2_group<6>(buf1, wlo, whi, 18, voff, c, gb1c, t0 + 17);
        c2_group<6>(buf1, wlo, whi, 24, voff, c, gb1c, t0 + 23);
        c2_group<4>(buf1, wlo, whi, 30, voff, c, gb1c, t0 + 29);
    }
    __syncthreads();

    // ---- D: h2 = relu(tconv1_bn(z2) + h1)   (buf2 slots 1..32, in place)
    {
        const float* wt1 = sm + OFF_WT1;
        float bias1c = sm[OFF_B1 + c];
        phaseD<6>(buf1, buf2, wt1, 0,  voff, c, bias1c);
        phaseD<6>(buf1, buf2, wt1, 6,  voff, c, bias1c);
        phaseD<6>(buf1, buf2, wt1, 12, voff, c, bias1c);
        phaseD<6>(buf1, buf2, wt1, 18, voff, c, bias1c);
        phaseD<6>(buf1, buf2, wt1, 24, voff, c, bias1c);
        phaseD<2>(buf1, buf2, wt1, 30, voff, c, bias1c);
    }

    // ---- FC: out[t][o] = fc_b[o] + sum_p h2[t][p] * fcwT[o][p]
    // 512 active threads: o = tid&63, tq = tid>>6 (4 t's per thread; 16 warps
    // active for latency hiding). Weight rows stride 340 -> conflict-free.
    u64 a0l = 0ull, a0h = 0ull, a1l = 0ull, a1h = 0ull;
    u64 a2l = 0ull, a2h = 0ull, a3l = 0ull, a3h = 0ull;
    const int o = tid & 63, tq = tid >> 6;
    for (int ch = 0; ch < 2; ch++) {
        const int p0 = ch * 336;
        __syncthreads();   // previous buf1 readers done; buf2 writes visible
        for (int i = tid; i < 64 * 336; i += 672) {
            int oo = i / 336, pi = i - oo * 336;
            buf1[oo * 340 + pi] = d_fcwT[oo * 672 + p0 + pi];
        }
        __syncthreads();
        if (tid < 512) {
            const float* wrow = buf1 + o * 340;
            const float* hb0  = buf2 + (tq * 4 + 1) * 672 + p0;
#pragma unroll 4
            for (int pi4 = 0; pi4 < 84; pi4++) {
                ulonglong2 w  = ld2x2(wrow + pi4 * 4);
                ulonglong2 h0 = ld2x2(hb0 + pi4 * 4);
                ulonglong2 h1 = ld2x2(hb0 + 672  + pi4 * 4);
                ulonglong2 h2 = ld2x2(hb0 + 1344 + pi4 * 4);
                ulonglong2 h3 = ld2x2(hb0 + 2016 + pi4 * 4);
                a0l = ffma2(w.x, h0.x, a0l);  a0h = ffma2(w.y, h0.y, a0h);
                a1l = ffma2(w.x, h1.x, a1l);  a1h = ffma2(w.y, h1.y, a1h);
                a2l = ffma2(w.x, h2.x, a2l);  a2h = ffma2(w.y, h2.y, a2h);
                a3l = ffma2(w.x, h3.x, a3l);  a3h = ffma2(w.y, h3.y, a3h);
            }
        }
    }
    if (tid < 512) {
        float bo = fcb[o];
        int tb = t0 + tq * 4;
        out[((b * 512 + tb + 0) * 2 + hand) * 64 + o] = hsum2(a0l) + hsum2(a0h) + bo;
        out[((b * 512 + tb + 1) * 2 + hand) * 64 + o] = hsum2(a1l) + hsum2(a1h) + bo;
        out[((b * 512 + tb + 2) * 2 + hand) * 64 + o] = hsum2(a2l) + hsum2(a2h) + bo;
        out[((b * 512 + tb + 3) * 2 + hand) * 64 + o] = hsum2(a3l) + hsum2(a3h) + bo;
    }
}

// ---------------------------------------------------------------------------
extern "C" void kernel_launch(void* const* d_in, const int* in_sizes, int n_in,
                              void* d_out, int out_size)
{
    const float* x        = (const float*)d_in[0];
    const float* gcn_w0   = (const float*)d_in[1];
    const float* gcn_b0   = (const float*)d_in[2];
    const float* tcn_w0   = (const float*)d_in[3];
    const float* tcn_b0   = (const float*)d_in[4];
    const float* bn_g0    = (const float*)d_in[5];
    const float* bn_b0    = (const float*)d_in[6];
    const float* bn_m0    = (const float*)d_in[7];
    const float* bn_v0    = (const float*)d_in[8];
    const float* res_w    = (const float*)d_in[9];
    const float* res_b    = (const float*)d_in[10];
    const float* res_bn_g = (const float*)d_in[11];
    const float* res_bn_b = (const float*)d_in[12];
    const float* res_bn_m = (const float*)d_in[13];
    const float* res_bn_v = (const float*)d_in[14];
    const float* gcn_w1   = (const float*)d_in[15];
    const float* gcn_b1   = (const float*)d_in[16];
    const float* tcn_w1   = (const float*)d_in[17];
    const float* tcn_b1   = (const float*)d_in[18];
    const float* bn_g1    = (const float*)d_in[19];
    const float* bn_b1    = (const float*)d_in[20];
    const float* bn_m1    = (const float*)d_in[21];
    const float* bn_v1    = (const float*)d_in[22];
    const float* fc_w     = (const float*)d_in[23];
    const float* fc_b     = (const float*)d_in[24];
    float* out = (float*)d_out;

    const size_t smem_bytes = (size_t)SM_TOTALF * sizeof(float);
    cudaFuncSetAttribute(stgcn_main, cudaFuncAttributeMaxDynamicSharedMemorySize,
                         (int)smem_bytes);

    stgcn_prep<<<96, 256>>>(gcn_w0, gcn_b0, tcn_w0, tcn_b0, bn_g0, bn_b0, bn_m0, bn_v0,
                            res_w, res_b, res_bn_g, res_bn_b, res_bn_m, res_bn_v,
                            gcn_w1, gcn_b1, tcn_w1, tcn_b1, bn_g1, bn_b1, bn_m1, bn_v1,
                            fc_w);
    stgcn_main<<<2048, 672, smem_bytes>>>(x, fc_b, out);
}